// round 11
// baseline (speedup 1.0000x reference)
#include <cuda_runtime.h>
#include <math.h>
#include <stdint.h>

#define Kq    4096
#define Mq    4
#define Dq    32
#define HWq   1024
#define EPSF  1e-7f
#define NEGINF -1e9f

// Output layout: [sample | code | one_hot | logit], all float32
#define SAMPLE_OFF 0ull
#define CODE_OFF   67108864ull
#define ONEHOT_OFF 67125248ull
#define LOGIT_OFF  134234112ull

__device__ float g_thresh[Mq * Kq];
__device__ float g_c2[Mq * Kq];

__device__ __forceinline__ void cp16(uint32_t dst_smem, const void* src) {
    asm volatile("cp.async.cg.shared.global [%0], [%1], 16;" :: "r"(dst_smem), "l"(src));
}
__device__ __forceinline__ void pfL2(const void* p) {
    asm volatile("prefetch.global.L2 [%0];" :: "l"(p));
}

// ---------------- Kernel 1: merged usage + thresh + codeword norms ----------------
// 32 blocks x 512 threads. Every block redundantly computes the usage count
// (64 KB scan, L2-resident after the first block), then its 512 thresholds.
__global__ void k_prep(const float* __restrict__ freq, const float* __restrict__ cb) {
    __shared__ int wsum[16];
    __shared__ float s_expo;
    const int tid = threadIdx.x;
    const int lane = tid & 31;

    int c = 0;
    #pragma unroll
    for (int i = tid; i < Mq * Kq; i += 512) c += (__ldg(freq + i) > EPSF) ? 1 : 0;
    for (int o = 16; o; o >>= 1) c += __shfl_down_sync(0xffffffffu, c, o);
    if (lane == 0) wsum[tid >> 5] = c;
    __syncthreads();
    if (tid == 0) {
        int t = 0;
        for (int w = 0; w < 16; ++w) t += wsum[w];
        float cu = (float)t * (1.0f / 16384.0f);
        cu = fminf(fmaxf(cu, 0.0f), 1.0f);
        s_expo = 12.0f - 11.0f * (cu * cu);   // -(BITS-1)*cu^2 + BITS
    }
    __syncthreads();

    const int i = blockIdx.x * 512 + tid;     // 32*512 = 16384
    const float4* c4 = (const float4*)(cb) + (size_t)i * 8;
    float s = 0.0f;
    #pragma unroll
    for (int j = 0; j < 8; ++j) {
        float4 v = c4[j];
        s += v.x * v.x + v.y * v.y + v.z * v.z + v.w * v.w;
    }
    g_c2[i] = s;
    float f = freq[i];
    float th = -1.0f;                          // drop >= 0 always -> never drop
    if (f > 0.0f) {
        double ie = 1.0 / (double)s_expo;
        th = (float)pow((double)f, ie);        // drop^e < f <=> drop < f^(1/e)
    }
    g_thresh[i] = th;
}

// ---------------- Kernel 2: fused main (R9 skeleton + L2 prefetch of dn/gn) -----
// 1024 blocks x 512 threads, 2 CTAs/SM. Block = one (n,m), 16 positions.
// Thread -> 4 consecutive k x 4 positions. Per tile:
//   fill -> commit -> L2-prefetch(next tile dn/gn) -> wait -> sync -> GEMM ->
//   epilogue -> sync.
// The prefetch (no dest regs) runs a full tile ahead, so epilogue LDG.cs hit
// L2 (~250cyc) instead of DRAM (~577cyc). No extra barriers, no reg pressure.
__global__ __launch_bounds__(512, 2) void k_main(
    const float* __restrict__ x, const float* __restrict__ cb,
    const float* __restrict__ temp,
    const float* __restrict__ drop, const float* __restrict__ gum,
    float* __restrict__ out)
{
    extern __shared__ float sm[];
    float* cbs  = sm;                    // 512 slots * 36 = 18432 floats (73.7 KB)
    float* xvs  = sm + 18432;            // 512 (16 pos x 32 d)
    float* x2s  = xvs + 512;             // 16
    float* scV  = x2s + 16;              // 64 (16 pos x 4 warps) logit argmax vals
    float* scV2 = scV + 64;              // 64 s argmax vals
    int*   scI  = (int*)(scV2 + 64);     // 64
    int*   scI2 = scI + 64;              // 64

    const int tid  = threadIdx.x;
    const int bid  = blockIdx.x;
    const int nm   = bid >> 6;           // 16 (n*M+m) values, 64 blocks each
    const int m    = nm & 3;
    const int hw0  = (bid & 63) << 4;    // 16 positions per block
    const long posBase = (long)nm * HWq + hw0;

    const int grp  = tid >> 7;           // 0..3 -> positions grp*4 .. grp*4+3
    const int jj   = tid & 127;          // k = t*512 + 4*jj + c
    const int wig  = (tid >> 5) & 3;     // warp within group
    const int lane = tid & 31;

    const size_t offBase = ((size_t)(posBase + grp * 4)) * Kq;

    // L2-prefetch decomposition: 128 threads/group cover 2 arrays x 4 pos x 16 lines
    const int pf_arr  = jj >> 6;         // 0: drop, 1: gum
    const int pf_pos  = (jj >> 4) & 3;   // position within group
    const int pf_line = jj & 15;         // 128B line within the 2KB per-pos chunk
    const float* pf_base = (pf_arr ? gum : drop) + offBase + (size_t)pf_pos * Kq + pf_line * 32;

    // Prefetch tile 0's dn/gn immediately (max lead time over the zero-fill below)
    pfL2(pf_base);

    // --- Zero-fill sample & one_hot first: pure stores, drain under the GEMM ---
    {
        const float4 z4 = make_float4(0.f, 0.f, 0.f, 0.f);
        float4* outS4 = (float4*)out;                     // SAMPLE_OFF = 0
        float4* outO4 = (float4*)(out + ONEHOT_OFF);
        const size_t base4 = (size_t)posBase * 1024;      // 16 pos * 1024 float4
        #pragma unroll
        for (int i = 0; i < 32; ++i) {
            __stcs(outS4 + base4 + i * 512 + tid, z4);
            __stcs(outO4 + base4 + i * 512 + tid, z4);
        }
    }

    // --- Load x vectors for the 16 positions (16 x 32 = 512 elems) ---
    {
        int p = tid & 15, d = tid >> 4;
        xvs[p * 32 + d] = x[((size_t)(nm * Dq + d)) * HWq + hw0 + p];
    }
    __syncthreads();
    if (tid < 16) {
        float s = 0.0f;
        #pragma unroll
        for (int d = 0; d < 32; ++d) { float v = xvs[tid * 32 + d]; s += v * v; }
        x2s[tid] = s;
    }
    __syncthreads();

    const float lbt = fmaxf(temp[m], EPSF);          // lower_bound(temperature)
    const float lsc = -0.015625f * lbt;              // (-1/64) * lb(temp)
    const float4* cb4 = (const float4*)(cb + (size_t)m * Kq * Dq);
    const float* c2m = g_c2 + m * Kq;
    const float* thm = g_thresh + m * Kq;
    const uint32_t cbs_base = (uint32_t)__cvta_generic_to_shared(cbs);

    float x2r[4];
    #pragma unroll
    for (int p = 0; p < 4; ++p) x2r[p] = x2s[grp * 4 + p];

    float lmv[4], smv[4]; int lix[4], six[4];
    #pragma unroll
    for (int p = 0; p < 4; ++p) { lmv[p] = -3.4e38f; smv[p] = -3.4e38f; lix[p] = 0; six[p] = 0; }

    for (int t = 0; t < 8; ++t) {
        // --- cp.async fill of 512-row tile into permuted stride-36 layout ---
        #pragma unroll
        for (int i = 0; i < 8; ++i) {
            int idx = i * 512 + tid;
            int row = idx >> 3, d4 = idx & 7;
            uint32_t dst = cbs_base + (uint32_t)((((row >> 2) + (row & 3) * 128) * 36 + d4 * 4) * 4);
            cp16(dst, cb4 + (size_t)(t * 512 + row) * 8 + d4);
        }
        asm volatile("cp.async.commit_group;");

        // --- L2-prefetch next tile's dn/gn (zero-register, one inst/thread) ---
        if (t < 7) pfL2(pf_base + (t + 1) * 512);

        asm volatile("cp.async.wait_group 0;");
        __syncthreads();

        // --- Register-tiled dots: 4 consecutive k x 4 positions ---
        float acc[4][4];
        #pragma unroll
        for (int c = 0; c < 4; ++c)
            #pragma unroll
            for (int p = 0; p < 4; ++p) acc[c][p] = 0.0f;

        #pragma unroll
        for (int dc = 0; dc < 8; ++dc) {
            float4 xp[4];
            #pragma unroll
            for (int p = 0; p < 4; ++p)
                xp[p] = *(const float4*)&xvs[(grp * 4 + p) * 32 + dc * 4];
            #pragma unroll
            for (int c = 0; c < 4; ++c) {
                const float4 cv = *(const float4*)&cbs[(c * 128 + jj) * 36 + dc * 4];
                #pragma unroll
                for (int p = 0; p < 4; ++p) {
                    acc[c][p] = fmaf(cv.x, xp[p].x, acc[c][p]);
                    acc[c][p] = fmaf(cv.y, xp[p].y, acc[c][p]);
                    acc[c][p] = fmaf(cv.z, xp[p].z, acc[c][p]);
                    acc[c][p] = fmaf(cv.w, xp[p].w, acc[c][p]);
                }
            }
        }

        // --- Epilogue: vector loads, logit/s, streaming 128-bit stores, argmaxes ---
        {
            const int k0 = t * 512 + 4 * jj;
            const float4 c2 = __ldg((const float4*)(c2m + k0));
            const float4 th = __ldg((const float4*)(thm + k0));
            #pragma unroll
            for (int p = 0; p < 4; ++p) {
                const size_t off = offBase + (size_t)p * Kq + k0;
                const float4 dn = __ldcs((const float4*)(drop + off));
                const float4 gn = __ldcs((const float4*)(gum  + off));
                float4 lg;
                lg.x = ((x2r[p] + c2.x) - 2.0f * acc[0][p]) * lsc;
                lg.y = ((x2r[p] + c2.y) - 2.0f * acc[1][p]) * lsc;
                lg.z = ((x2r[p] + c2.z) - 2.0f * acc[2][p]) * lsc;
                lg.w = ((x2r[p] + c2.w) - 2.0f * acc[3][p]) * lsc;
                if (dn.x < th.x) lg.x += NEGINF;
                if (dn.y < th.y) lg.y += NEGINF;
                if (dn.z < th.z) lg.z += NEGINF;
                if (dn.w < th.w) lg.w += NEGINF;
                __stcs((float4*)(out + LOGIT_OFF + off), lg);
                // running argmaxes (k ascending in thread -> strict > keeps lowest)
                if (lg.x > lmv[p]) { lmv[p] = lg.x; lix[p] = k0 + 0; }
                if (lg.y > lmv[p]) { lmv[p] = lg.y; lix[p] = k0 + 1; }
                if (lg.z > lmv[p]) { lmv[p] = lg.z; lix[p] = k0 + 2; }
                if (lg.w > lmv[p]) { lmv[p] = lg.w; lix[p] = k0 + 3; }
                float sv;
                sv = lg.x + gn.x; if (sv > smv[p]) { smv[p] = sv; six[p] = k0 + 0; }
                sv = lg.y + gn.y; if (sv > smv[p]) { smv[p] = sv; six[p] = k0 + 1; }
                sv = lg.z + gn.z; if (sv > smv[p]) { smv[p] = sv; six[p] = k0 + 2; }
                sv = lg.w + gn.w; if (sv > smv[p]) { smv[p] = sv; six[p] = k0 + 3; }
            }
        }
        __syncthreads();   // all reads of cbs done before next fill overwrites
    }

    // --- Block-wide argmax reductions (tie -> lowest k, matching jnp.argmax) ---
    #pragma unroll
    for (int p = 0; p < 4; ++p) {
        int pp = grp * 4 + p;
        float v = lmv[p]; int ix = lix[p];
        for (int o = 16; o; o >>= 1) {
            float ov = __shfl_down_sync(0xffffffffu, v, o);
            int   oi = __shfl_down_sync(0xffffffffu, ix, o);
            if (ov > v || (ov == v && oi < ix)) { v = ov; ix = oi; }
        }
        if (lane == 0) { scV[pp * 4 + wig] = v; scI[pp * 4 + wig] = ix; }
        v = smv[p]; ix = six[p];
        for (int o = 16; o; o >>= 1) {
            float ov = __shfl_down_sync(0xffffffffu, v, o);
            int   oi = __shfl_down_sync(0xffffffffu, ix, o);
            if (ov > v || (ov == v && oi < ix)) { v = ov; ix = oi; }
        }
        if (lane == 0) { scV2[pp * 4 + wig] = v; scI2[pp * 4 + wig] = ix; }
    }
    __syncthreads();   // also orders the zero-fill stores before the scatters below

    if (tid < 16) {
        float bv = -3.4e38f; int li = 0;
        for (int w = 0; w < 4; ++w) {
            float v = scV[tid * 4 + w]; int i2 = scI[tid * 4 + w];
            if (v > bv || (v == bv && i2 < li)) { bv = v; li = i2; }
        }
        bv = -3.4e38f; int si = 0;
        for (int w = 0; w < 4; ++w) {
            float v = scV2[tid * 4 + w]; int i2 = scI2[tid * 4 + w];
            if (v > bv || (v == bv && i2 < si)) { bv = v; si = i2; }
        }
        size_t base = ((size_t)(posBase + tid)) * Kq;
        out[CODE_OFF + (size_t)(posBase + tid)] = (float)li;
        out[ONEHOT_OFF + base + li] = 1.0f;
        out[SAMPLE_OFF + base + si] = 1.0f;   // (1+y)-y == 1.0 within 1 ulp
    }
}

// ---------------- launch ----------------
extern "C" void kernel_launch(void* const* d_in, const int* in_sizes, int n_in,
                              void* d_out, int out_size) {
    const float* x    = (const float*)d_in[0];
    const float* cb   = (const float*)d_in[1];
    const float* freq = (const float*)d_in[2];
    const float* temp = (const float*)d_in[3];
    const float* drop = (const float*)d_in[4];
    const float* gum  = (const float*)d_in[5];
    float* out = (float*)d_out;

    const int smemBytes = (18432 + 512 + 16 + 64 * 4) * 4;  // ~76.9 KB
    cudaFuncSetAttribute(k_main, cudaFuncAttributeMaxDynamicSharedMemorySize, smemBytes);

    k_prep<<<32, 512>>>(freq, cb);
    k_main<<<1024, 512, smemBytes>>>(x, cb, temp, drop, gum, out);
}

// round 12
// speedup vs baseline: 1.1386x; 1.1386x over previous
#include <cuda_runtime.h>
#include <math.h>
#include <stdint.h>

#define Kq    4096
#define Mq    4
#define Dq    32
#define HWq   1024
#define EPSF  1e-7f
#define NEGINF -1e9f

// Output layout: [sample | code | one_hot | logit], all float32
#define SAMPLE_OFF 0ull
#define CODE_OFF   67108864ull
#define ONEHOT_OFF 67125248ull
#define LOGIT_OFF  134234112ull

__device__ float g_thresh[Mq * Kq];
__device__ float g_c2[Mq * Kq];

__device__ __forceinline__ void cp16(uint32_t dst_smem, const void* src) {
    asm volatile("cp.async.cg.shared.global [%0], [%1], 16;" :: "r"(dst_smem), "l"(src));
}

// ---------------- Kernel 1: merged usage + thresh + codeword norms ----------------
// 32 blocks x 512 threads. Every block redundantly computes the usage count
// (64 KB scan, L2-resident after the first block), then its 512 thresholds.
__global__ void k_prep(const float* __restrict__ freq, const float* __restrict__ cb) {
    __shared__ int wsum[16];
    __shared__ float s_expo;
    const int tid = threadIdx.x;
    const int lane = tid & 31;

    int c = 0;
    #pragma unroll
    for (int i = tid; i < Mq * Kq; i += 512) c += (__ldg(freq + i) > EPSF) ? 1 : 0;
    for (int o = 16; o; o >>= 1) c += __shfl_down_sync(0xffffffffu, c, o);
    if (lane == 0) wsum[tid >> 5] = c;
    __syncthreads();
    if (tid == 0) {
        int t = 0;
        for (int w = 0; w < 16; ++w) t += wsum[w];
        float cu = (float)t * (1.0f / 16384.0f);
        cu = fminf(fmaxf(cu, 0.0f), 1.0f);
        s_expo = 12.0f - 11.0f * (cu * cu);   // -(BITS-1)*cu^2 + BITS
    }
    __syncthreads();

    const int i = blockIdx.x * 512 + tid;     // 32*512 = 16384
    const float4* c4 = (const float4*)(cb) + (size_t)i * 8;
    float s = 0.0f;
    #pragma unroll
    for (int j = 0; j < 8; ++j) {
        float4 v = c4[j];
        s += v.x * v.x + v.y * v.y + v.z * v.z + v.w * v.w;
    }
    g_c2[i] = s;
    float f = freq[i];
    float th = -1.0f;                          // drop >= 0 always -> never drop
    if (f > 0.0f) {
        double ie = 1.0 / (double)s_expo;
        th = (float)pow((double)f, ie);        // drop^e < f <=> drop < f^(1/e)
    }
    g_thresh[i] = th;
}

// ---------------- Kernel 2: fused main (R9 skeleton + pipelined epilogue) -------
// 1024 blocks x 512 threads, 2 CTAs/SM. Block = one (n,m), 16 positions.
// Thread -> 4 consecutive k x 4 positions. Per tile:
//   fill -> commit -> wait -> sync -> [c2/th loads] -> GEMM -> epilogue -> sync.
// Epilogue is software-pipelined: p+1's dn/gn are in flight while p computes
// (MLP>=2 on the DRAM chain). c2/th load under the GEMM's latency shadow.
__global__ __launch_bounds__(512, 2) void k_main(
    const float* __restrict__ x, const float* __restrict__ cb,
    const float* __restrict__ temp,
    const float* __restrict__ drop, const float* __restrict__ gum,
    float* __restrict__ out)
{
    extern __shared__ float sm[];
    float* cbs  = sm;                    // 512 slots * 36 = 18432 floats (73.7 KB)
    float* xvs  = sm + 18432;            // 512 (16 pos x 32 d)
    float* x2s  = xvs + 512;             // 16
    float* scV  = x2s + 16;              // 64 (16 pos x 4 warps) logit argmax vals
    float* scV2 = scV + 64;              // 64 s argmax vals
    int*   scI  = (int*)(scV2 + 64);     // 64
    int*   scI2 = scI + 64;              // 64

    const int tid  = threadIdx.x;
    const int bid  = blockIdx.x;
    const int nm   = bid >> 6;           // 16 (n*M+m) values, 64 blocks each
    const int m    = nm & 3;
    const int hw0  = (bid & 63) << 4;    // 16 positions per block
    const long posBase = (long)nm * HWq + hw0;

    const int grp  = tid >> 7;           // 0..3 -> positions grp*4 .. grp*4+3
    const int jj   = tid & 127;          // k = t*512 + 4*jj + c
    const int wig  = (tid >> 5) & 3;     // warp within group
    const int lane = tid & 31;

    // --- Zero-fill sample & one_hot first: pure stores, drain under the GEMM ---
    {
        const float4 z4 = make_float4(0.f, 0.f, 0.f, 0.f);
        float4* outS4 = (float4*)out;                     // SAMPLE_OFF = 0
        float4* outO4 = (float4*)(out + ONEHOT_OFF);
        const size_t base4 = (size_t)posBase * 1024;      // 16 pos * 1024 float4
        #pragma unroll
        for (int i = 0; i < 32; ++i) {
            __stcs(outS4 + base4 + i * 512 + tid, z4);
            __stcs(outO4 + base4 + i * 512 + tid, z4);
        }
    }

    // --- Load x vectors for the 16 positions (16 x 32 = 512 elems) ---
    {
        int p = tid & 15, d = tid >> 4;
        xvs[p * 32 + d] = x[((size_t)(nm * Dq + d)) * HWq + hw0 + p];
    }
    __syncthreads();
    if (tid < 16) {
        float s = 0.0f;
        #pragma unroll
        for (int d = 0; d < 32; ++d) { float v = xvs[tid * 32 + d]; s += v * v; }
        x2s[tid] = s;
    }
    __syncthreads();

    const float lbt = fmaxf(temp[m], EPSF);          // lower_bound(temperature)
    const float lsc = -0.015625f * lbt;              // (-1/64) * lb(temp)
    const float4* cb4 = (const float4*)(cb + (size_t)m * Kq * Dq);
    const float* c2m = g_c2 + m * Kq;
    const float* thm = g_thresh + m * Kq;
    const uint32_t cbs_base = (uint32_t)__cvta_generic_to_shared(cbs);

    float x2r[4];
    #pragma unroll
    for (int p = 0; p < 4; ++p) x2r[p] = x2s[grp * 4 + p];
    const size_t offBase = ((size_t)(posBase + grp * 4)) * Kq;

    float lmv[4], smv[4]; int lix[4], six[4];
    #pragma unroll
    for (int p = 0; p < 4; ++p) { lmv[p] = -3.4e38f; smv[p] = -3.4e38f; lix[p] = 0; six[p] = 0; }

    for (int t = 0; t < 8; ++t) {
        // --- cp.async fill of 512-row tile into permuted stride-36 layout ---
        #pragma unroll
        for (int i = 0; i < 8; ++i) {
            int idx = i * 512 + tid;
            int row = idx >> 3, d4 = idx & 7;
            uint32_t dst = cbs_base + (uint32_t)((((row >> 2) + (row & 3) * 128) * 36 + d4 * 4) * 4);
            cp16(dst, cb4 + (size_t)(t * 512 + row) * 8 + d4);
        }
        asm volatile("cp.async.commit_group;");
        asm volatile("cp.async.wait_group 0;");
        __syncthreads();

        // Hoist per-k constants: their L2 latency hides under the GEMM below.
        const int k0 = t * 512 + 4 * jj;
        const float4 c2 = __ldg((const float4*)(c2m + k0));
        const float4 th = __ldg((const float4*)(thm + k0));

        // --- Register-tiled dots: 4 consecutive k x 4 positions ---
        float acc[4][4];
        #pragma unroll
        for (int c = 0; c < 4; ++c)
            #pragma unroll
            for (int p = 0; p < 4; ++p) acc[c][p] = 0.0f;

        #pragma unroll
        for (int dc = 0; dc < 8; ++dc) {
            float4 xp[4];
            #pragma unroll
            for (int p = 0; p < 4; ++p)
                xp[p] = *(const float4*)&xvs[(grp * 4 + p) * 32 + dc * 4];
            #pragma unroll
            for (int c = 0; c < 4; ++c) {
                const float4 cv = *(const float4*)&cbs[(c * 128 + jj) * 36 + dc * 4];
                #pragma unroll
                for (int p = 0; p < 4; ++p) {
                    acc[c][p] = fmaf(cv.x, xp[p].x, acc[c][p]);
                    acc[c][p] = fmaf(cv.y, xp[p].y, acc[c][p]);
                    acc[c][p] = fmaf(cv.z, xp[p].z, acc[c][p]);
                    acc[c][p] = fmaf(cv.w, xp[p].w, acc[c][p]);
                }
            }
        }

        // --- Epilogue: software-pipelined over positions (next loads in flight
        //     while current position computes) ---
        {
            float4 dn = __ldcs((const float4*)(drop + offBase + k0));
            float4 gn = __ldcs((const float4*)(gum  + offBase + k0));
            #pragma unroll
            for (int p = 0; p < 4; ++p) {
                float4 dnn, gnn;
                if (p < 3) {
                    const size_t offn = offBase + (size_t)(p + 1) * Kq + k0;
                    dnn = __ldcs((const float4*)(drop + offn));
                    gnn = __ldcs((const float4*)(gum  + offn));
                }
                const size_t off = offBase + (size_t)p * Kq + k0;
                float4 lg;
                lg.x = ((x2r[p] + c2.x) - 2.0f * acc[0][p]) * lsc;
                lg.y = ((x2r[p] + c2.y) - 2.0f * acc[1][p]) * lsc;
                lg.z = ((x2r[p] + c2.z) - 2.0f * acc[2][p]) * lsc;
                lg.w = ((x2r[p] + c2.w) - 2.0f * acc[3][p]) * lsc;
                if (dn.x < th.x) lg.x += NEGINF;
                if (dn.y < th.y) lg.y += NEGINF;
                if (dn.z < th.z) lg.z += NEGINF;
                if (dn.w < th.w) lg.w += NEGINF;
                __stcs((float4*)(out + LOGIT_OFF + off), lg);
                // running argmaxes (k ascending in thread -> strict > keeps lowest)
                if (lg.x > lmv[p]) { lmv[p] = lg.x; lix[p] = k0 + 0; }
                if (lg.y > lmv[p]) { lmv[p] = lg.y; lix[p] = k0 + 1; }
                if (lg.z > lmv[p]) { lmv[p] = lg.z; lix[p] = k0 + 2; }
                if (lg.w > lmv[p]) { lmv[p] = lg.w; lix[p] = k0 + 3; }
                float sv;
                sv = lg.x + gn.x; if (sv > smv[p]) { smv[p] = sv; six[p] = k0 + 0; }
                sv = lg.y + gn.y; if (sv > smv[p]) { smv[p] = sv; six[p] = k0 + 1; }
                sv = lg.z + gn.z; if (sv > smv[p]) { smv[p] = sv; six[p] = k0 + 2; }
                sv = lg.w + gn.w; if (sv > smv[p]) { smv[p] = sv; six[p] = k0 + 3; }
                dn = dnn; gn = gnn;
            }
        }
        __syncthreads();   // all reads of cbs done before next fill overwrites
    }

    // --- Block-wide argmax reductions (tie -> lowest k, matching jnp.argmax) ---
    #pragma unroll
    for (int p = 0; p < 4; ++p) {
        int pp = grp * 4 + p;
        float v = lmv[p]; int ix = lix[p];
        for (int o = 16; o; o >>= 1) {
            float ov = __shfl_down_sync(0xffffffffu, v, o);
            int   oi = __shfl_down_sync(0xffffffffu, ix, o);
            if (ov > v || (ov == v && oi < ix)) { v = ov; ix = oi; }
        }
        if (lane == 0) { scV[pp * 4 + wig] = v; scI[pp * 4 + wig] = ix; }
        v = smv[p]; ix = six[p];
        for (int o = 16; o; o >>= 1) {
            float ov = __shfl_down_sync(0xffffffffu, v, o);
            int   oi = __shfl_down_sync(0xffffffffu, ix, o);
            if (ov > v || (ov == v && oi < ix)) { v = ov; ix = oi; }
        }
        if (lane == 0) { scV2[pp * 4 + wig] = v; scI2[pp * 4 + wig] = ix; }
    }
    __syncthreads();   // also orders the zero-fill stores before the scatters below

    if (tid < 16) {
        float bv = -3.4e38f; int li = 0;
        for (int w = 0; w < 4; ++w) {
            float v = scV[tid * 4 + w]; int i2 = scI[tid * 4 + w];
            if (v > bv || (v == bv && i2 < li)) { bv = v; li = i2; }
        }
        bv = -3.4e38f; int si = 0;
        for (int w = 0; w < 4; ++w) {
            float v = scV2[tid * 4 + w]; int i2 = scI2[tid * 4 + w];
            if (v > bv || (v == bv && i2 < si)) { bv = v; si = i2; }
        }
        size_t base = ((size_t)(posBase + tid)) * Kq;
        out[CODE_OFF + (size_t)(posBase + tid)] = (float)li;
        out[ONEHOT_OFF + base + li] = 1.0f;
        out[SAMPLE_OFF + base + si] = 1.0f;   // (1+y)-y == 1.0 within 1 ulp
    }
}

// ---------------- launch ----------------
extern "C" void kernel_launch(void* const* d_in, const int* in_sizes, int n_in,
                              void* d_out, int out_size) {
    const float* x    = (const float*)d_in[0];
    const float* cb   = (const float*)d_in[1];
    const float* freq = (const float*)d_in[2];
    const float* temp = (const float*)d_in[3];
    const float* drop = (const float*)d_in[4];
    const float* gum  = (const float*)d_in[5];
    float* out = (float*)d_out;

    const int smemBytes = (18432 + 512 + 16 + 64 * 4) * 4;  // ~76.9 KB
    cudaFuncSetAttribute(k_main, cudaFuncAttributeMaxDynamicSharedMemorySize, smemBytes);

    k_prep<<<32, 512>>>(freq, cb);
    k_main<<<1024, 512, smemBytes>>>(x, cb, temp, drop, gum, out);
}